// round 2
// baseline (speedup 1.0000x reference)
#include <cuda_runtime.h>

#define IN_F   4096
#define OUT_F  4096
#define TOKENS 4096

// Scratch for the materialized weight (alloc-free rule: __device__ global).
__device__ float g_W[(size_t)OUT_F * IN_F];

// ---------------------------------------------------------------------------
// Kernel 1: W = mu + softplus(rho) * eps   (vectorized float4)
// ---------------------------------------------------------------------------
__global__ void materialize_w_kernel(const float4* __restrict__ mu,
                                     const float4* __restrict__ rho,
                                     const float4* __restrict__ eps) {
    int i = blockIdx.x * blockDim.x + threadIdx.x;
    float4 m = mu[i];
    float4 r = rho[i];
    float4 e = eps[i];
    float4 w;
    w.x = fmaf(log1pf(__expf(r.x)), e.x, m.x);
    w.y = fmaf(log1pf(__expf(r.y)), e.y, m.y);
    w.z = fmaf(log1pf(__expf(r.z)), e.z, m.z);
    w.w = fmaf(log1pf(__expf(r.w)), e.w, m.w);
    reinterpret_cast<float4*>(g_W)[i] = w;
}

// ---------------------------------------------------------------------------
// Kernel 2: C[T, O] = X[T, I] @ W[O, I]^T + bias[O]
// 128x128 tile SGEMM, BK=8, 256 threads, 8x8 per-thread micro-tile.
// Bias is computed inline in the epilogue from raw (mu, rho, eps) inputs —
// do NOT pass a __device__ global's name as a host-side kernel argument
// (resolves to the host shadow symbol; ATS silently reads zeros).
// ---------------------------------------------------------------------------
#define BM 128
#define BN 128
#define BK 8
#define TM 8
#define TN 8

__global__ __launch_bounds__(256, 2)
void sgemm_xbt_kernel(const float* __restrict__ A,      // X [TOKENS, IN_F]
                      const float* __restrict__ bmu,    // [OUT_F]
                      const float* __restrict__ brho,   // [OUT_F]
                      const float* __restrict__ beps,   // [OUT_F]
                      float* __restrict__ C) {          // [TOKENS, OUT_F]
    __shared__ float As[BK][BM];
    __shared__ float Bs[BK][BN];

    const float* B = g_W;  // [OUT_F, IN_F] — device-side symbol reference: OK

    const int bx = blockIdx.x;           // N tile index (output features)
    const int by = blockIdx.y;           // M tile index (tokens)
    const int tid = (int)threadIdx.x;    // 0..255
    const int tx = tid % 16;             // micro-tile col group
    const int ty = tid / 16;             // micro-tile row group

    const int lrow = tid >> 1;           // 0..127
    const int lcol = (tid & 1) * 4;      // 0 or 4

    const float* Aptr = A + (size_t)(by * BM + lrow) * IN_F + lcol;
    const float* Bptr = B + (size_t)(bx * BN + lrow) * IN_F + lcol;

    float acc[TM][TN];
#pragma unroll
    for (int i = 0; i < TM; i++)
#pragma unroll
        for (int j = 0; j < TN; j++) acc[i][j] = 0.0f;

    for (int k0 = 0; k0 < IN_F; k0 += BK) {
        float4 a = *reinterpret_cast<const float4*>(Aptr + k0);
        float4 b = *reinterpret_cast<const float4*>(Bptr + k0);

        As[lcol + 0][lrow] = a.x;
        As[lcol + 1][lrow] = a.y;
        As[lcol + 2][lrow] = a.z;
        As[lcol + 3][lrow] = a.w;
        Bs[lcol + 0][lrow] = b.x;
        Bs[lcol + 1][lrow] = b.y;
        Bs[lcol + 2][lrow] = b.z;
        Bs[lcol + 3][lrow] = b.w;
        __syncthreads();

#pragma unroll
        for (int k = 0; k < BK; k++) {
            float ar[TM], br[TN];
            float4 a0 = *reinterpret_cast<const float4*>(&As[k][ty * TM]);
            float4 a1 = *reinterpret_cast<const float4*>(&As[k][ty * TM + 4]);
            float4 b0 = *reinterpret_cast<const float4*>(&Bs[k][tx * TN]);
            float4 b1 = *reinterpret_cast<const float4*>(&Bs[k][tx * TN + 4]);
            ar[0] = a0.x; ar[1] = a0.y; ar[2] = a0.z; ar[3] = a0.w;
            ar[4] = a1.x; ar[5] = a1.y; ar[6] = a1.z; ar[7] = a1.w;
            br[0] = b0.x; br[1] = b0.y; br[2] = b0.z; br[3] = b0.w;
            br[4] = b1.x; br[5] = b1.y; br[6] = b1.z; br[7] = b1.w;
#pragma unroll
            for (int i = 0; i < TM; i++)
#pragma unroll
                for (int j = 0; j < TN; j++)
                    acc[i][j] = fmaf(ar[i], br[j], acc[i][j]);
        }
        __syncthreads();
    }

    // Epilogue: compute bias inline (mu + softplus(rho)*eps), add, write out.
    const int col0 = bx * BN + tx * TN;
    float bv[TN];
#pragma unroll
    for (int j = 0; j < TN; j++) {
        const int c = col0 + j;
        bv[j] = fmaf(log1pf(__expf(brho[c])), beps[c], bmu[c]);
    }

#pragma unroll
    for (int i = 0; i < TM; i++) {
        const int row = by * BM + ty * TM + i;
        float* crow = C + (size_t)row * OUT_F + col0;
        float4 o0, o1;
        o0.x = acc[i][0] + bv[0];
        o0.y = acc[i][1] + bv[1];
        o0.z = acc[i][2] + bv[2];
        o0.w = acc[i][3] + bv[3];
        o1.x = acc[i][4] + bv[4];
        o1.y = acc[i][5] + bv[5];
        o1.z = acc[i][6] + bv[6];
        o1.w = acc[i][7] + bv[7];
        *reinterpret_cast<float4*>(crow)     = o0;
        *reinterpret_cast<float4*>(crow + 4) = o1;
    }
}

// ---------------------------------------------------------------------------
// Inputs in metadata order:
//   0: x            [TOKENS, IN_F]
//   1: weight_mu    [OUT_F, IN_F]
//   2: weight_rho   [OUT_F, IN_F]
//   3: bias_mu      [OUT_F]
//   4: bias_rho     [OUT_F]
//   5: weight_eps   [OUT_F, IN_F]
//   6: bias_eps     [OUT_F]
// ---------------------------------------------------------------------------
extern "C" void kernel_launch(void* const* d_in, const int* in_sizes, int n_in,
                              void* d_out, int out_size) {
    const float* x    = (const float*)d_in[0];
    const float* wmu  = (const float*)d_in[1];
    const float* wrho = (const float*)d_in[2];
    const float* bmu  = (const float*)d_in[3];
    const float* brho = (const float*)d_in[4];
    const float* weps = (const float*)d_in[5];
    const float* beps = (const float*)d_in[6];
    float* out = (float*)d_out;

    // W materialization: 4194304 float4 elements
    {
        int total4 = (OUT_F * IN_F) / 4;
        int threads = 256;
        int blocks = total4 / threads;
        materialize_w_kernel<<<blocks, threads>>>(
            (const float4*)wmu, (const float4*)wrho, (const float4*)weps);
    }

    // GEMM with fused bias epilogue
    {
        dim3 grid(OUT_F / BN, TOKENS / BM);
        sgemm_xbt_kernel<<<grid, 256>>>(x, bmu, brho, beps, out);
    }
}

// round 4
// speedup vs baseline: 3.8393x; 3.8393x over previous
#include <cuda_runtime.h>
#include <cstdint>

#define IN_F   4096
#define OUT_F  4096
#define TOKENS 4096

// GEMM tiling
#define BM 128
#define BN 128
#define BK 32
#define NK (IN_F / BK)        // 128 iterations
#define STAGES 3

// Smem: A/B tiles padded to stride 36 floats (conflict-free frag loads)
#define LDS_STRIDE 36
#define A_TILE_B   (BM * LDS_STRIDE * 4)        // 18432 bytes
#define STAGE_B    (2 * A_TILE_B)               // 36864 bytes (A then B)
#define OFF_BIAS   (STAGES * STAGE_B)           // 110592
#define SMEM_TOTAL (OFF_BIAS + BN * 4)          // 111104

// ---------------------------------------------------------------------------
// Device scratch (alloc-free rule): tf32-rounded X and W, stored as fp32 bits.
// Referenced ONLY from device code (host-shadow trap!).
// ---------------------------------------------------------------------------
__device__ uint32_t g_X[(size_t)TOKENS * IN_F];
__device__ uint32_t g_W[(size_t)OUT_F * IN_F];

// ---------------------------------------------------------------------------
// helpers
// ---------------------------------------------------------------------------
__device__ __forceinline__ uint32_t smem_u32(const void* p) {
    uint32_t a;
    asm("{ .reg .u64 t; cvta.to.shared.u64 t, %1; cvt.u32.u64 %0, t; }"
        : "=r"(a) : "l"(p));
    return a;
}
__device__ __forceinline__ void cp16(uint32_t dst, const void* src) {
    asm volatile("cp.async.cg.shared.global [%0], [%1], 16;" :: "r"(dst), "l"(src));
}
#define CP_COMMIT() asm volatile("cp.async.commit_group;" ::: "memory")
#define CP_WAIT(N)  asm volatile("cp.async.wait_group %0;" :: "n"(N) : "memory")

__device__ __forceinline__ uint32_t f2tf32(float f) {
    uint32_t r;
    asm("cvt.rna.tf32.f32 %0, %1;" : "=r"(r) : "f"(f));
    return r;
}

__device__ __forceinline__ void mma_tf32(float* d, const uint32_t* a, const uint32_t* b) {
    asm volatile(
        "mma.sync.aligned.m16n8k8.row.col.f32.tf32.tf32.f32 "
        "{%0,%1,%2,%3}, {%4,%5,%6,%7}, {%8,%9}, {%0,%1,%2,%3};"
        : "+f"(d[0]), "+f"(d[1]), "+f"(d[2]), "+f"(d[3])
        : "r"(a[0]), "r"(a[1]), "r"(a[2]), "r"(a[3]), "r"(b[0]), "r"(b[1]));
}

// ---------------------------------------------------------------------------
// Pre-pass 1: W = tf32(mu + softplus(rho)*eps)
// ---------------------------------------------------------------------------
__global__ void prep_w_kernel(const float4* __restrict__ mu,
                              const float4* __restrict__ rho,
                              const float4* __restrict__ eps) {
    int i = blockIdx.x * blockDim.x + threadIdx.x;
    float4 m = mu[i], r = rho[i], e = eps[i];
    uint4 o;
    o.x = f2tf32(fmaf(log1pf(__expf(r.x)), e.x, m.x));
    o.y = f2tf32(fmaf(log1pf(__expf(r.y)), e.y, m.y));
    o.z = f2tf32(fmaf(log1pf(__expf(r.z)), e.z, m.z));
    o.w = f2tf32(fmaf(log1pf(__expf(r.w)), e.w, m.w));
    reinterpret_cast<uint4*>(g_W)[i] = o;
}

// Pre-pass 2: X -> tf32
__global__ void prep_x_kernel(const float4* __restrict__ x) {
    int i = blockIdx.x * blockDim.x + threadIdx.x;
    float4 v = x[i];
    uint4 o;
    o.x = f2tf32(v.x);
    o.y = f2tf32(v.y);
    o.z = f2tf32(v.z);
    o.w = f2tf32(v.w);
    reinterpret_cast<uint4*>(g_X)[i] = o;
}

// ---------------------------------------------------------------------------
// tf32 HMMA GEMM: C[T,O] = X @ W^T + bias (bias fused; softplus inline)
// 128x128 CTA tile, BK=32, 3-stage cp.async pipeline.
// 8 warps: warpM = wid%4 (32 rows each), warpN = wid/4 (64 cols each).
// Warp tile 32x64 -> 2 m16 tiles x 8 n8 tiles, k in 4 steps of 8.
// ---------------------------------------------------------------------------
__device__ __forceinline__ void load_stage(uint32_t sbase, int stg, int kidx,
                                           int bx, int by, int tid) {
    const uint32_t st = sbase + stg * STAGE_B;
    const int k0 = kidx * BK;
    // A: 128 rows x 32 floats (8 x 16B chunks per row)
    #pragma unroll
    for (int it = 0; it < 4; it++) {
        int idx = tid + it * 256;
        int row = idx >> 3, ch = idx & 7;
        cp16(st + row * (LDS_STRIDE * 4) + ch * 16,
             g_X + (size_t)(by * BM + row) * IN_F + k0 + ch * 4);
    }
    // B: 128 rows (out-features) x 32 floats
    #pragma unroll
    for (int it = 0; it < 4; it++) {
        int idx = tid + it * 256;
        int row = idx >> 3, ch = idx & 7;
        cp16(st + A_TILE_B + row * (LDS_STRIDE * 4) + ch * 16,
             g_W + (size_t)(bx * BN + row) * IN_F + k0 + ch * 4);
    }
}

__global__ __launch_bounds__(256, 2)
void gemm_tf32_kernel(const float* __restrict__ bmu,
                      const float* __restrict__ brho,
                      const float* __restrict__ beps,
                      float* __restrict__ C) {
    extern __shared__ char smem[];
    const uint32_t sbase = smem_u32(smem);
    const int tid = (int)threadIdx.x;
    const int wid = tid >> 5;
    const int lane = tid & 31;
    const int la = lane >> 2;          // 0..7
    const int lb = lane & 3;           // 0..3
    const int warpM = wid & 3;         // 4 warps along M
    const int warpN = wid >> 2;        // 2 warps along N
    const int bx = blockIdx.x;         // N tile
    const int by = blockIdx.y;         // M tile

    // Fused bias into smem
    float* sb = reinterpret_cast<float*>(smem + OFF_BIAS);
    if (tid < BN) {
        int col = bx * BN + tid;
        sb[tid] = fmaf(log1pf(__expf(brho[col])), beps[col], bmu[col]);
    }

    float d[2][8][4];
    #pragma unroll
    for (int mi = 0; mi < 2; mi++)
        #pragma unroll
        for (int ni = 0; ni < 8; ni++)
            #pragma unroll
            for (int j = 0; j < 4; j++) d[mi][ni][j] = 0.0f;

    // Prologue: fill all stages
    #pragma unroll
    for (int s = 0; s < STAGES; s++) {
        load_stage(sbase, s, s, bx, by, tid);
        CP_COMMIT();
    }

    for (int i = 0; i < NK; i++) {
        CP_WAIT(STAGES - 1);
        __syncthreads();

        const int stg = i % STAGES;
        const uint32_t* As = reinterpret_cast<const uint32_t*>(smem + stg * STAGE_B);
        const uint32_t* Bs = reinterpret_cast<const uint32_t*>(smem + stg * STAGE_B + A_TILE_B);

        #pragma unroll
        for (int s = 0; s < 4; s++) {          // k-steps of 8
            const int ck = s * 8 + lb;
            uint32_t a[2][4];
            #pragma unroll
            for (int mi = 0; mi < 2; mi++) {
                const int base = (warpM * 32 + mi * 16 + la) * LDS_STRIDE + ck;
                a[mi][0] = As[base];
                a[mi][1] = As[base + 8 * LDS_STRIDE];
                a[mi][2] = As[base + 4];
                a[mi][3] = As[base + 8 * LDS_STRIDE + 4];
            }
            #pragma unroll
            for (int ni = 0; ni < 8; ni++) {
                const int bbase = (warpN * 64 + ni * 8 + la) * LDS_STRIDE + ck;
                uint32_t b[2];
                b[0] = Bs[bbase];
                b[1] = Bs[bbase + 4];
                mma_tf32(d[0][ni], a[0], b);
                mma_tf32(d[1][ni], a[1], b);
            }
        }

        __syncthreads();
        if (i + STAGES < NK)
            load_stage(sbase, stg, i + STAGES, bx, by, tid);
        CP_COMMIT();
    }

    // Epilogue: add bias, write float2 per fragment half
    #pragma unroll
    for (int mi = 0; mi < 2; mi++) {
        const int row0 = by * BM + warpM * 32 + mi * 16 + la;
        #pragma unroll
        for (int ni = 0; ni < 8; ni++) {
            const int cl = warpN * 64 + ni * 8 + 2 * lb;   // local col
            const int col = bx * BN + cl;
            float2 o0, o1;
            o0.x = d[mi][ni][0] + sb[cl];
            o0.y = d[mi][ni][1] + sb[cl + 1];
            o1.x = d[mi][ni][2] + sb[cl];
            o1.y = d[mi][ni][3] + sb[cl + 1];
            *reinterpret_cast<float2*>(C + (size_t)row0 * OUT_F + col)       = o0;
            *reinterpret_cast<float2*>(C + (size_t)(row0 + 8) * OUT_F + col) = o1;
        }
    }
}

// ---------------------------------------------------------------------------
// Inputs (metadata order):
//   0: x [T,I]  1: weight_mu [O,I]  2: weight_rho [O,I]
//   3: bias_mu [O]  4: bias_rho [O]  5: weight_eps [O,I]  6: bias_eps [O]
// ---------------------------------------------------------------------------
extern "C" void kernel_launch(void* const* d_in, const int* in_sizes, int n_in,
                              void* d_out, int out_size) {
    const float* x    = (const float*)d_in[0];
    const float* wmu  = (const float*)d_in[1];
    const float* wrho = (const float*)d_in[2];
    const float* bmu  = (const float*)d_in[3];
    const float* brho = (const float*)d_in[4];
    const float* weps = (const float*)d_in[5];
    const float* beps = (const float*)d_in[6];
    float* out = (float*)d_out;

    {
        int total4 = (OUT_F * IN_F) / 4;
        prep_w_kernel<<<total4 / 256, 256>>>(
            (const float4*)wmu, (const float4*)wrho, (const float4*)weps);
        prep_x_kernel<<<(TOKENS * IN_F / 4) / 256, 256>>>((const float4*)x);
    }

    cudaFuncSetAttribute(gemm_tf32_kernel,
                         cudaFuncAttributeMaxDynamicSharedMemorySize, SMEM_TOTAL);
    dim3 grid(OUT_F / BN, TOKENS / BM);   // (32, 32)
    gemm_tf32_kernel<<<grid, 256, SMEM_TOTAL>>>(bmu, brho, beps, out);
}